// round 14
// baseline (speedup 1.0000x reference)
#include <cuda_runtime.h>
#include <cuda_fp16.h>
#include <cstdint>

// ---------------- problem constants ----------------
#define NNODE 512
#define FD    17949
#define NE    4096
#define H2D   768
#define EMBD  128
#define QN    1536
#define OUTD  35898

#define KPAD1 18048            // 564*32
#define CH1   564
#define NSPLIT 6               // 94 chunks per split; 6*4*6 = 144 CTAs = one wave
#define KPAD2 768
#define CH2   24
#define NDPAD 36096            // 141*256 padded N-rows for W_d3

// ---------------- fp32 scratch ----------------
#define OFF_A    0
#define OFF_DEG  (NNODE*NNODE)
#define OFF_Q    (OFF_DEG + NNODE)
#define OFF_T1   (OFF_Q + NNODE*QN)
#define OFF_H    (OFF_T1 + NNODE*H2D)
#define OFF_HD   (OFF_H + NNODE*H2D)
#define OFF_P    (OFF_HD + NNODE*H2D)
#define SCRATCH_SZ (OFF_P + NSPLIT*NNODE*QN)
__device__ float g_scratch[SCRATCH_SZ];

// ---------------- fp16 buffers (zero-initialized statics) ----------------
__device__ __align__(16) unsigned short g_xh[NNODE*KPAD1], g_xl[NNODE*KPAD1];
__device__ __align__(16) unsigned short g_vh[QN*KPAD1];              // V single fp16
__device__ __align__(16) unsigned short g_wh[NDPAD*KPAD2];           // W_d3 single fp16
__device__ __align__(16) unsigned short g_hh[NNODE*KPAD2], g_hl[NNODE*KPAD2];

// ---------------- PTX helpers (sm_80-level; safe under compute_103) ----------------
__device__ __forceinline__ unsigned smem_u32(const void* p) {
    unsigned a;
    asm("{ .reg .u64 t; cvta.to.shared.u64 t, %1; cvt.u32.u64 %0, t; }" : "=r"(a) : "l"(p));
    return a;
}
__device__ __forceinline__ void cp16(unsigned dst, const void* src) {
    asm volatile("cp.async.cg.shared.global [%0], [%1], 16;" :: "r"(dst), "l"(src) : "memory");
}
__device__ __forceinline__ void ldsm4(unsigned r[4], unsigned addr) {
    asm volatile("ldmatrix.sync.aligned.m8n8.x4.shared.b16 {%0,%1,%2,%3}, [%4];"
                 : "=r"(r[0]), "=r"(r[1]), "=r"(r[2]), "=r"(r[3]) : "r"(addr));
}
__device__ __forceinline__ void mma16816(float c[4], const unsigned a[4],
                                         unsigned b0, unsigned b1) {
    asm volatile("mma.sync.aligned.m16n8k16.row.col.f32.f16.f16.f32 "
                 "{%0,%1,%2,%3}, {%4,%5,%6,%7}, {%8,%9}, {%0,%1,%2,%3};"
                 : "+f"(c[0]), "+f"(c[1]), "+f"(c[2]), "+f"(c[3])
                 : "r"(a[0]), "r"(a[1]), "r"(a[2]), "r"(a[3]), "r"(b0), "r"(b1));
}

// ---------------- fp16 hi/lo split (A matrices) ----------------
template <int KQ8>
__global__ void k_split_f(const float* __restrict__ src, unsigned short* __restrict__ hi,
                          unsigned short* __restrict__ lo, int rows, int K, int zc0) {
    const int idx = blockIdx.x * 256 + threadIdx.x;
    if (idx >= rows * KQ8) return;
    const int r  = idx / KQ8;
    const int k0 = (idx - r * KQ8) * 8;
    const int Kpad = KQ8 * 8;
    const float* s = src + (long long)r * K;
    float v[8];
#pragma unroll
    for (int j = 0; j < 8; j++) {
        int k = k0 + j;
        v[j] = (k < K) ? __ldg(s + k) : 0.0f;
    }
    if (zc0 && k0 == 0) v[0] = 0.0f;
    unsigned hu[4], lu[4];
#pragma unroll
    for (int j = 0; j < 4; j++) {
        __half h0 = __float2half_rn(v[2 * j]);
        __half h1 = __float2half_rn(v[2 * j + 1]);
        __half l0 = __float2half_rn(v[2 * j] - __half2float(h0));
        __half l1 = __float2half_rn(v[2 * j + 1] - __half2float(h1));
        hu[j] = ((unsigned)__half_as_ushort(h1) << 16) | (unsigned)__half_as_ushort(h0);
        lu[j] = ((unsigned)__half_as_ushort(l1) << 16) | (unsigned)__half_as_ushort(l0);
    }
    const long long o = (long long)r * Kpad + k0;
    *(uint4*)(hi + o) = make_uint4(hu[0], hu[1], hu[2], hu[3]);
    *(uint4*)(lo + o) = make_uint4(lu[0], lu[1], lu[2], lu[3]);
}

// ---------------- fp16 single convert (B matrices) ----------------
template <int KQ8>
__global__ void k_cvt(const float* __restrict__ src, unsigned short* __restrict__ dst,
                      int rows, int K) {
    const int idx = blockIdx.x * 256 + threadIdx.x;
    if (idx >= rows * KQ8) return;
    const int r  = idx / KQ8;
    const int k0 = (idx - r * KQ8) * 8;
    const int Kpad = KQ8 * 8;
    const float* s = src + (long long)r * K;
    unsigned u[4];
#pragma unroll
    for (int j = 0; j < 4; j++) {
        int k = k0 + 2 * j;
        float f0 = (k < K) ? __ldg(s + k) : 0.0f;
        float f1 = (k + 1 < K) ? __ldg(s + k + 1) : 0.0f;
        __half h0 = __float2half_rn(f0), h1 = __float2half_rn(f1);
        u[j] = ((unsigned)__half_as_ushort(h1) << 16) | (unsigned)__half_as_ushort(h0);
    }
    *(uint4*)(dst + (long long)r * Kpad + k0) = make_uint4(u[0], u[1], u[2], u[3]);
}

// ---------------- split-K combine ----------------
__global__ void k_combine(const float* __restrict__ P, float* __restrict__ Q) {
    int i = blockIdx.x * blockDim.x + threadIdx.x;
    if (i < NNODE * QN) {
        float s = 0.0f;
#pragma unroll
        for (int z = 0; z < NSPLIT; z++) s += P[z * NNODE * QN + i];
        Q[i] = s;
    }
}

// ---------------- HMMA NT GEMM: C = A[M,K]*B[N,K]^T, fp16 2-product, fp32 out ------------
// BM=128, BN=256, BK=32. 512 thr = 16 warps (2 m x 8 n), warp tile 64x32.
// 4-stage cp.async; stage = Ah(10240)|Al(10240)|B(20480) = 40960 B.
#define STAGE_B 40960u
template <bool BIAS, bool SWAPXY>
__global__ __launch_bounds__(512, 1)
void gemm_mma(const unsigned short* __restrict__ Ah, const unsigned short* __restrict__ Al, int lda,
              const unsigned short* __restrict__ B, int ldb,
              const float* __restrict__ bias, float* __restrict__ C, int ldc, int Ncols,
              long long zstride, int chunks_total, int nsplit) {
    extern __shared__ __align__(16) char smem[];
    const unsigned sb = smem_u32(smem);
    const int tid = threadIdx.x;
    const int lane = tid & 31, wid = tid >> 5;
    const int warp_m = wid & 1, warp_n = wid >> 1;      // 2 x 8
    const int bm = (SWAPXY ? blockIdx.x : blockIdx.y) * 128;
    const int bn = (SWAPXY ? blockIdx.y : blockIdx.x) * 256;
    const int z = blockIdx.z;
    const int cn = chunks_total / nsplit;
    const int c0 = z * cn;

    // loader: lrow = tid>>2 (0..127), lseg = tid&3
    const int lrow = tid >> 2;
    const int lseg = tid & 3;
    const unsigned adst = (unsigned)(lrow * 80 + lseg * 16);
    const long long a_src  = (long long)(bm + lrow) * lda + lseg * 8;
    const long long b_src0 = (long long)(bn + lrow) * ldb + lseg * 8;
    const long long b_src1 = (long long)(bn + lrow + 128) * ldb + lseg * 8;

    // ldmatrix lane bases
    const unsigned a_lane = (unsigned)((warp_m * 64 + (lane & 7) + ((lane & 8) ? 8 : 0)) * 80
                                       + ((lane & 16) ? 16 : 0));
    const unsigned b_lane = (unsigned)((warp_n * 32 + (lane & 7) + ((lane & 16) ? 8 : 0)) * 80
                                       + ((lane & 8) ? 16 : 0));

    float acc[4][4][4];
#pragma unroll
    for (int mi = 0; mi < 4; mi++)
#pragma unroll
        for (int ni = 0; ni < 4; ni++)
#pragma unroll
            for (int e = 0; e < 4; e++) acc[mi][ni][e] = 0.0f;

    auto issue = [&](int chunk, int buf) {
        const unsigned st = sb + (unsigned)buf * STAGE_B;
        const long long ko = (long long)chunk * 32;
        cp16(st + adst,            Ah + a_src + ko);
        cp16(st + 10240u + adst,   Al + a_src + ko);
        cp16(st + 20480u + adst,   B + b_src0 + ko);
        cp16(st + 30720u + adst,   B + b_src1 + ko);
        asm volatile("cp.async.commit_group;" ::: "memory");
    };

    issue(c0, 0);
    issue(c0 + 1, 1);
    issue(c0 + 2, 2);

    int buf_t = 0;
    for (int t = 0; t < cn; t++) {
        if (t + 3 < cn) {
            issue(c0 + t + 3, (buf_t + 3) & 3);
            asm volatile("cp.async.wait_group 3;" ::: "memory");
        } else if (t + 2 < cn) {
            asm volatile("cp.async.wait_group 2;" ::: "memory");
        } else if (t + 1 < cn) {
            asm volatile("cp.async.wait_group 1;" ::: "memory");
        } else {
            asm volatile("cp.async.wait_group 0;" ::: "memory");
        }
        __syncthreads();
        const unsigned st = sb + (unsigned)buf_t * STAGE_B;
#pragma unroll
        for (int ks = 0; ks < 2; ks++) {
            unsigned bf[2][4];
#pragma unroll
            for (int p = 0; p < 2; p++)
                ldsm4(bf[p], st + 20480u + b_lane + p * 1280u + ks * 32u);
#pragma unroll
            for (int mi = 0; mi < 4; mi++) {
                unsigned ah[4], al[4];
                ldsm4(ah, st + a_lane + mi * 1280u + ks * 32u);
                ldsm4(al, st + 10240u + a_lane + mi * 1280u + ks * 32u);
#pragma unroll
                for (int ni = 0; ni < 4; ni++) {
                    const int p = ni >> 1, h = (ni & 1) * 2;
                    mma16816(acc[mi][ni], ah, bf[p][h], bf[p][h + 1]);  // hi_A * B
                    mma16816(acc[mi][ni], al, bf[p][h], bf[p][h + 1]);  // lo_A * B
                }
            }
        }
        __syncthreads();
        buf_t = (buf_t + 1) & 3;
    }

    // epilogue
    float* Cz = C + z * zstride;
    const int er = bm + warp_m * 64 + (lane >> 2);
    const int ec = bn + warp_n * 32 + (lane & 3) * 2;
#pragma unroll
    for (int mi = 0; mi < 4; mi++)
#pragma unroll
        for (int ni = 0; ni < 4; ni++) {
            const int col = ec + ni * 8;
            if (col < Ncols) {
                float bv0 = BIAS ? bias[col] : 0.0f;
                float bv1 = BIAS ? bias[col + 1] : 0.0f;
                const int row = er + mi * 16;
                *(float2*)&Cz[(long long)row * ldc + col] =
                    make_float2(acc[mi][ni][0] + bv0, acc[mi][ni][1] + bv1);
                *(float2*)&Cz[(long long)(row + 8) * ldc + col] =
                    make_float2(acc[mi][ni][2] + bv0, acc[mi][ni][3] + bv1);
            }
        }
}

// ---------------- adjacency build ----------------
__global__ void k_zero(float* scratch) {
    int i = blockIdx.x * blockDim.x + threadIdx.x;
    if (i < NNODE * NNODE + NNODE) scratch[i] = 0.0f;
}
__global__ void k_count(float* scratch, const int* __restrict__ src,
                        const int* __restrict__ dst) {
    int e = blockIdx.x * blockDim.x + threadIdx.x;
    if (e < NE) {
        int d = dst[e], s = src[e];
        atomicAdd(&scratch[OFF_A + d * NNODE + s], 1.0f);
        atomicAdd(&scratch[OFF_DEG + d], 1.0f);
    }
}
__global__ void k_norm(float* scratch) {
    int i = blockIdx.x * blockDim.x + threadIdx.x;
    if (i < NNODE * NNODE) {
        float d = scratch[OFF_DEG + (i >> 9)];
        scratch[OFF_A + i] = scratch[OFF_A + i] / fmaxf(d, 1.0f);
    }
}

// ---------------- FFMA2 SIMT kernels (mid-size GEMMs; validated) ----------------
__device__ __forceinline__ unsigned long long pack2(float a, float b) {
    unsigned long long r;
    asm("mov.b64 %0, {%1, %2};" : "=l"(r) : "f"(a), "f"(b));
    return r;
}
__device__ __forceinline__ void unpack2(unsigned long long v, float& a, float& b) {
    asm("mov.b64 {%0, %1}, %2;" : "=f"(a), "=f"(b) : "l"(v));
}
__device__ __forceinline__ unsigned long long ffma2(unsigned long long a,
                                                    unsigned long long b,
                                                    unsigned long long c) {
    unsigned long long d;
    asm("fma.rn.f32x2 %0, %1, %2, %3;" : "=l"(d) : "l"(a), "l"(b), "l"(c));
    return d;
}

template <int BM, int BN, int TM, int TN>
__device__ __forceinline__ void compute_tile(const float (*As)[BM + 4],
                                             const float (*Bs)[BN + 4],
                                             int ty, int tx,
                                             unsigned long long acc[TM / 2][TN]) {
#pragma unroll
    for (int kk = 0; kk < 16; kk++) {
        unsigned long long aa[TM / 2];
#pragma unroll
        for (int i = 0; i < TM / 2; i += 2) {
            ulonglong2 av = *reinterpret_cast<const ulonglong2*>(&As[kk][ty * TM + 2 * i]);
            aa[i] = av.x;
            if (i + 1 < TM / 2) aa[i + 1] = av.y;
        }
        float4 bvv = *reinterpret_cast<const float4*>(&Bs[kk][tx * TN]);
        unsigned long long bb[4];
        bb[0] = pack2(bvv.x, bvv.x);
        bb[1] = pack2(bvv.y, bvv.y);
        bb[2] = pack2(bvv.z, bvv.z);
        bb[3] = pack2(bvv.w, bvv.w);
#pragma unroll
        for (int i = 0; i < TM / 2; i++)
#pragma unroll
            for (int j = 0; j < TN; j++)
                acc[i][j] = ffma2(aa[i], bb[j], acc[i][j]);
    }
}

template <int BM, int BN, int TM, int TN, bool ZC0, bool RELU, bool BIAS>
__global__ __launch_bounds__(256, 2)
void gemm_nt(const float* __restrict__ A, int lda,
             const float* __restrict__ B, int ldb,
             const float* __restrict__ bias,
             float* __restrict__ C, int ldc,
             int Ncols, int K) {
    constexpr int BK = 16;
    __shared__ float As[BK][BM + 4];
    __shared__ float Bs[BK][BN + 4];
    const int tid = threadIdx.x;
    const int tx = tid & 15, ty = tid >> 4;
    const int bm = blockIdx.y * BM, bn = blockIdx.x * BN;
    const int lm = tid >> 4, lk = tid & 15;
    constexpr int ASL = BM * BK / 256, BSL = BN * BK / 256;
    float ar[ASL], br[BSL];
    unsigned long long acc[TM / 2][TN];
#pragma unroll
    for (int i = 0; i < TM / 2; i++)
#pragma unroll
        for (int j = 0; j < TN; j++) acc[i][j] = 0ull;
    const int ktiles = (K + BK - 1) / BK;
    {
        const int k = lk;
#pragma unroll
        for (int s = 0; s < ASL; s++) {
            float v = 0.0f;
            if (k < K) { v = A[(bm + lm + s * 16) * lda + k]; if (ZC0 && k == 0) v = 0.0f; }
            ar[s] = v;
        }
#pragma unroll
        for (int s = 0; s < BSL; s++) {
            int n = bn + lm + s * 16;
            float v = 0.0f;
            if (k < K && n < Ncols) v = B[n * ldb + k];
            br[s] = v;
        }
    }
    for (int t = 0; t < ktiles; t++) {
        __syncthreads();
#pragma unroll
        for (int s = 0; s < ASL; s++) As[lk][lm + s * 16] = ar[s];
#pragma unroll
        for (int s = 0; s < BSL; s++) Bs[lk][lm + s * 16] = br[s];
        __syncthreads();
        if (t + 1 < ktiles) {
            const int k = (t + 1) * BK + lk;
#pragma unroll
            for (int s = 0; s < ASL; s++) {
                float v = 0.0f;
                if (k < K) { v = A[(bm + lm + s * 16) * lda + k]; if (ZC0 && k == 0) v = 0.0f; }
                ar[s] = v;
            }
#pragma unroll
            for (int s = 0; s < BSL; s++) {
                int n = bn + lm + s * 16;
                float v = 0.0f;
                if (k < K && n < Ncols) v = B[n * ldb + k];
                br[s] = v;
            }
        }
        compute_tile<BM, BN, TM, TN>(As, Bs, ty, tx, acc);
    }
#pragma unroll
    for (int j = 0; j < TN; j++) {
        const int n = bn + tx * TN + j;
        if (n >= Ncols) continue;
        float bv = BIAS ? bias[n] : 0.0f;
#pragma unroll
        for (int i = 0; i < TM / 2; i++) {
            float c0, c1;
            unpack2(acc[i][j], c0, c1);
            c0 += bv; c1 += bv;
            if (RELU) { c0 = fmaxf(c0, 0.0f); c1 = fmaxf(c1, 0.0f); }
            const int m0 = bm + ty * TM + 2 * i;
            C[m0 * ldc + n] = c0;
            C[(m0 + 1) * ldc + n] = c1;
        }
    }
}

template <int MODE>
__global__ __launch_bounds__(256, 2)
void gemm_nn64(const float* __restrict__ A, int lda,
               const float* __restrict__ B, int ldb, int jstr,
               const float* __restrict__ qeven, const float* __restrict__ bias,
               float* __restrict__ C, int ldc, int K) {
    constexpr int BM = 64, BN = 64, BK = 16, TM = 4, TN = 4;
    __shared__ float As[BK][BM + 4];
    __shared__ float Bs[BK][BN + 4];
    const int tid = threadIdx.x;
    const int tx = tid & 15, ty = tid >> 4;
    const int bm = blockIdx.y * BM, bn = blockIdx.x * BN;
    const int lm = tid >> 4, lk = tid & 15;
    const int bkk = tid >> 6, bnn = tid & 63;
    float ar[4], br[4];
    unsigned long long acc[2][4];
#pragma unroll
    for (int i = 0; i < 2; i++)
#pragma unroll
        for (int j = 0; j < 4; j++) acc[i][j] = 0ull;
    const int ktiles = K / BK;
    {
#pragma unroll
        for (int s = 0; s < 4; s++) ar[s] = A[(bm + lm + s * 16) * lda + lk];
#pragma unroll
        for (int s = 0; s < 4; s++) br[s] = B[(bkk + s * 4) * ldb + (bn + bnn) * jstr];
    }
    for (int t = 0; t < ktiles; t++) {
        __syncthreads();
#pragma unroll
        for (int s = 0; s < 4; s++) As[lk][lm + s * 16] = ar[s];
#pragma unroll
        for (int s = 0; s < 4; s++) Bs[bkk + s * 4][bnn] = br[s];
        __syncthreads();
        if (t + 1 < ktiles) {
            const int k0 = (t + 1) * BK;
#pragma unroll
            for (int s = 0; s < 4; s++) ar[s] = A[(bm + lm + s * 16) * lda + k0 + lk];
#pragma unroll
            for (int s = 0; s < 4; s++)
                br[s] = B[(k0 + bkk + s * 4) * ldb + (bn + bnn) * jstr];
        }
        compute_tile<BM, BN, TM, TN>(As, Bs, ty, tx, acc);
    }
#pragma unroll
    for (int j = 0; j < 4; j++) {
        const int n = bn + tx * TN + j;
#pragma unroll
        for (int i = 0; i < 2; i++) {
            float c0, c1;
            unpack2(acc[i][j], c0, c1);
            const int m0 = bm + ty * TM + 2 * i;
            if (MODE == 1) {
                float bv = bias[n];
                c0 = fmaxf(c0 + qeven[m0 * QN + 2 * n] + bv, 0.0f);
                c1 = fmaxf(c1 + qeven[(m0 + 1) * QN + 2 * n] + bv, 0.0f);
            }
            C[m0 * ldc + n] = c0;
            C[(m0 + 1) * ldc + n] = c1;
        }
    }
}

// ---------------- launcher ----------------
extern "C" void kernel_launch(void* const* d_in, const int* in_sizes, int n_in,
                              void* d_out, int out_size) {
    (void)in_sizes; (void)n_in; (void)out_size;
    const float* x    = (const float*)d_in[0];
    const int*   esrc = (const int*)d_in[1];
    const int*   edst = (const int*)d_in[2];
    const float* W_e2 = (const float*)d_in[3];
    const float* b_e2 = (const float*)d_in[4];
    const float* W_e3 = (const float*)d_in[5];
    const float* b_e3 = (const float*)d_in[6];
    const float* W_d1 = (const float*)d_in[7];
    const float* b_d1 = (const float*)d_in[8];
    const float* W_d3 = (const float*)d_in[9];
    const float* b_d3 = (const float*)d_in[10];

    float* out = (float*)d_out;
    float* enc = out;
    float* dec = out + NNODE * EMBD;

    float* scratch = nullptr;
    cudaGetSymbolAddress((void**)&scratch, g_scratch);
    float* A_  = scratch + OFF_A;
    float* Q_  = scratch + OFF_Q;
    float* T1_ = scratch + OFF_T1;
    float* H_  = scratch + OFF_H;
    float* HD_ = scratch + OFF_HD;
    float* P_  = scratch + OFF_P;

    unsigned short *xh, *xl, *vh, *wh, *hh, *hl;
    cudaGetSymbolAddress((void**)&xh, g_xh); cudaGetSymbolAddress((void**)&xl, g_xl);
    cudaGetSymbolAddress((void**)&vh, g_vh);
    cudaGetSymbolAddress((void**)&wh, g_wh);
    cudaGetSymbolAddress((void**)&hh, g_hh); cudaGetSymbolAddress((void**)&hl, g_hl);

    static int smem_set = 0;
    if (!smem_set) {
        cudaFuncSetAttribute(gemm_mma<false, false>,
                             cudaFuncAttributeMaxDynamicSharedMemorySize, 4 * STAGE_B);
        cudaFuncSetAttribute(gemm_mma<true, true>,
                             cudaFuncAttributeMaxDynamicSharedMemorySize, 4 * STAGE_B);
        smem_set = 1;
    }

    const int KQ8a = KPAD1 / 8;   // 2256
    const int KQ8b = KPAD2 / 8;   // 96

    // launches 1-3: fp16 conversions (x split; V, W_d3 single)
    k_split_f<KPAD1 / 8><<<(NNODE * KQ8a + 255) / 256, 256>>>(x, xh, xl, NNODE, FD, 1);
    k_cvt<KPAD1 / 8><<<(QN * KQ8a + 255) / 256, 256>>>(W_e2, vh, QN, FD);
    k_cvt<KPAD2 / 8><<<(OUTD * KQ8b + 255) / 256, 256>>>(W_d3, wh, OUTD, H2D);

    // launches 4-5: adjacency accumulation (norm deferred; not needed before GEMM1)
    k_zero <<<(NNODE * NNODE + NNODE + 255) / 256, 256>>>(scratch);
    k_count<<<(NE + 255) / 256, 256>>>(scratch, esrc, edst);

    // launch 6 (ncu -s 5 -c 1 profiles this): Q = x' @ V^T, split-K=6
    gemm_mma<false, false><<<dim3(QN / 256, NNODE / 128, NSPLIT), 512, 4 * STAGE_B>>>(
        xh, xl, KPAD1, vh, KPAD1, nullptr, P_, QN, QN,
        (long long)NNODE * QN, CH1, NSPLIT);

    k_norm <<<(NNODE * NNODE + 255) / 256, 256>>>(scratch);
    k_combine<<<(NNODE * QN + 255) / 256, 256>>>(P_, Q_);

    // T1 = A @ Qodd
    gemm_nn64<0><<<dim3(H2D / 64, NNODE / 64), 256>>>(
        A_, NNODE, Q_ + 1, QN, 2, nullptr, nullptr, T1_, H2D, NNODE);

    // H = relu(Qeven + A @ T1 + b_e2)
    gemm_nn64<1><<<dim3(H2D / 64, NNODE / 64), 256>>>(
        A_, NNODE, T1_, H2D, 1, Q_, b_e2, H_, H2D, NNODE);

    // encoded = H @ W_e3^T + b_e3
    gemm_nt<64, 64, 4, 4, false, false, true>
        <<<dim3(EMBD / 64, NNODE / 64), 256>>>(H_, H2D, W_e3, H2D, b_e3, enc, EMBD, EMBD, H2D);

    // HD = relu(encoded @ W_d1^T + b_d1)
    gemm_nt<64, 64, 4, 4, false, true, true>
        <<<dim3(H2D / 64, NNODE / 64), 256>>>(enc, EMBD, W_d1, EMBD, b_d1, HD_, H2D, H2D, EMBD);

    // split HD (fp16 h/l), then decoded = HD @ W_d3^T + b_d3
    k_split_f<KPAD2 / 8><<<(NNODE * KQ8b + 255) / 256, 256>>>(HD_, hh, hl, NNODE, H2D, 0);
    gemm_mma<true, true><<<dim3(NNODE / 128, NDPAD / 256, 1), 512, 4 * STAGE_B>>>(
        hh, hl, KPAD2, wh, KPAD2, b_d3, dec, OUTD, OUTD,
        0ll, CH2, 1);
}

// round 15
// speedup vs baseline: 1.2553x; 1.2553x over previous
#include <cuda_runtime.h>
#include <cuda_bf16.h>
#include <cstdint>

// ---------------- problem constants ----------------
#define NNODE 512
#define FD    17949
#define NE    4096
#define H2D   768
#define EMBD  128
#define QN    1536
#define OUTD  35898

#define KPAD1 18048            // 564*32
#define CH1   564
#define NSPLIT 6               // 94 chunks per split; 6*4*6 = 144 CTAs = one wave
#define KPAD2 768
#define CH2   24
#define NDPAD 36096            // 141*256 padded N-rows for W_d3

// ---------------- fp32 scratch ----------------
#define OFF_A    0
#define OFF_DEG  (NNODE*NNODE)
#define OFF_Q    (OFF_DEG + NNODE)
#define OFF_T1   (OFF_Q + NNODE*QN)
#define OFF_H    (OFF_T1 + NNODE*H2D)
#define OFF_HD   (OFF_H + NNODE*H2D)
#define OFF_P    (OFF_HD + NNODE*H2D)
#define SCRATCH_SZ (OFF_P + NSPLIT*NNODE*QN)
__device__ float g_scratch[SCRATCH_SZ];

// ---------------- bf16 split buffers (zero-initialized statics) ----------------
__device__ __align__(16) unsigned short g_xh[NNODE*KPAD1], g_xl[NNODE*KPAD1];
__device__ __align__(16) unsigned short g_vh[QN*KPAD1],    g_vl[QN*KPAD1];
__device__ __align__(16) unsigned short g_wh[NDPAD*KPAD2], g_wl[NDPAD*KPAD2];
__device__ __align__(16) unsigned short g_hh[NNODE*KPAD2], g_hl[NNODE*KPAD2];

// ---------------- PTX helpers (sm_80-level; safe under compute_103) ----------------
__device__ __forceinline__ unsigned smem_u32(const void* p) {
    unsigned a;
    asm("{ .reg .u64 t; cvta.to.shared.u64 t, %1; cvt.u32.u64 %0, t; }" : "=r"(a) : "l"(p));
    return a;
}
__device__ __forceinline__ void cp16(unsigned dst, const void* src) {
    asm volatile("cp.async.cg.shared.global [%0], [%1], 16;" :: "r"(dst), "l"(src) : "memory");
}
__device__ __forceinline__ void ldsm4(unsigned r[4], unsigned addr) {
    asm volatile("ldmatrix.sync.aligned.m8n8.x4.shared.b16 {%0,%1,%2,%3}, [%4];"
                 : "=r"(r[0]), "=r"(r[1]), "=r"(r[2]), "=r"(r[3]) : "r"(addr));
}
__device__ __forceinline__ void mma16816(float c[4], const unsigned a[4],
                                         unsigned b0, unsigned b1) {
    asm volatile("mma.sync.aligned.m16n8k16.row.col.f32.bf16.bf16.f32 "
                 "{%0,%1,%2,%3}, {%4,%5,%6,%7}, {%8,%9}, {%0,%1,%2,%3};"
                 : "+f"(c[0]), "+f"(c[1]), "+f"(c[2]), "+f"(c[3])
                 : "r"(a[0]), "r"(a[1]), "r"(a[2]), "r"(a[3]), "r"(b0), "r"(b1));
}

// ---------------- fast bf16 hi/lo split ----------------
template <int KQ8>
__global__ void k_split_f(const float* __restrict__ src, unsigned short* __restrict__ hi,
                          unsigned short* __restrict__ lo, int rows, int K, int zc0) {
    const int idx = blockIdx.x * 256 + threadIdx.x;
    if (idx >= rows * KQ8) return;
    const int r  = idx / KQ8;
    const int k0 = (idx - r * KQ8) * 8;
    const int Kpad = KQ8 * 8;
    const float* s = src + (long long)r * K;
    float v[8];
#pragma unroll
    for (int j = 0; j < 8; j++) {
        int k = k0 + j;
        v[j] = (k < K) ? __ldg(s + k) : 0.0f;
    }
    if (zc0 && k0 == 0) v[0] = 0.0f;
    unsigned hu[4], lu[4];
#pragma unroll
    for (int j = 0; j < 4; j++) {
        __nv_bfloat16 h0 = __float2bfloat16(v[2 * j]);
        __nv_bfloat16 h1 = __float2bfloat16(v[2 * j + 1]);
        __nv_bfloat16 l0 = __float2bfloat16(v[2 * j] - __bfloat162float(h0));
        __nv_bfloat16 l1 = __float2bfloat16(v[2 * j + 1] - __bfloat162float(h1));
        hu[j] = ((unsigned)__bfloat16_as_ushort(h1) << 16) | (unsigned)__bfloat16_as_ushort(h0);
        lu[j] = ((unsigned)__bfloat16_as_ushort(l1) << 16) | (unsigned)__bfloat16_as_ushort(l0);
    }
    const long long o = (long long)r * Kpad + k0;
    *(uint4*)(hi + o) = make_uint4(hu[0], hu[1], hu[2], hu[3]);
    *(uint4*)(lo + o) = make_uint4(lu[0], lu[1], lu[2], lu[3]);
}

// ---------------- split-K combine ----------------
__global__ void k_combine(const float* __restrict__ P, float* __restrict__ Q) {
    int i = blockIdx.x * blockDim.x + threadIdx.x;
    if (i < NNODE * QN) {
        float s = 0.0f;
#pragma unroll
        for (int z = 0; z < NSPLIT; z++) s += P[z * NNODE * QN + i];
        Q[i] = s;
    }
}

// ---------------- HMMA NT GEMM: C = A[M,K]*B[N,K]^T, bf16 hi/lo 3-product, fp32 out ----------
// BM=128, BN=256, BK=32. 512 thr = 16 warps (2 m x 8 n), warp tile 64x32.
// 3-stage cp.async, ONE barrier per iteration (cutlass multistage pattern).
// stage = Ah(10240)|Al(10240)|Bh(20480)|Bl(20480) = 61440 B.
#define STAGE_B 61440u
template <bool BIAS, bool SWAPXY>
__global__ __launch_bounds__(512, 1)
void gemm_mma(const unsigned short* __restrict__ Ah, const unsigned short* __restrict__ Al, int lda,
              const unsigned short* __restrict__ Bh, const unsigned short* __restrict__ Bl, int ldb,
              const float* __restrict__ bias, float* __restrict__ C, int ldc, int Ncols,
              long long zstride, int chunks_total, int nsplit) {
    extern __shared__ __align__(16) char smem[];
    const unsigned sb = smem_u32(smem);
    const int tid = threadIdx.x;
    const int lane = tid & 31, wid = tid >> 5;
    const int warp_m = wid & 1, warp_n = wid >> 1;      // 2 x 8
    const int bm = (SWAPXY ? blockIdx.x : blockIdx.y) * 128;
    const int bn = (SWAPXY ? blockIdx.y : blockIdx.x) * 256;
    const int z = blockIdx.z;
    const int cn = chunks_total / nsplit;
    const int c0 = z * cn;

    // loader: lrow = tid>>2 (0..127), lseg = tid&3 ; A 1 row, B rows lrow and lrow+128
    const int lrow = tid >> 2;
    const int lseg = tid & 3;
    const unsigned adst = (unsigned)(lrow * 80 + lseg * 16);
    const long long a_src  = (long long)(bm + lrow) * lda + lseg * 8;
    const long long b_src0 = (long long)(bn + lrow) * ldb + lseg * 8;
    const long long b_src1 = (long long)(bn + lrow + 128) * ldb + lseg * 8;

    // ldmatrix lane bases
    const unsigned a_lane = (unsigned)((warp_m * 64 + (lane & 7) + ((lane & 8) ? 8 : 0)) * 80
                                       + ((lane & 16) ? 16 : 0));
    const unsigned b_lane = (unsigned)((warp_n * 32 + (lane & 7) + ((lane & 16) ? 8 : 0)) * 80
                                       + ((lane & 8) ? 16 : 0));

    float acc[4][4][4];
#pragma unroll
    for (int mi = 0; mi < 4; mi++)
#pragma unroll
        for (int ni = 0; ni < 4; ni++)
#pragma unroll
            for (int e = 0; e < 4; e++) acc[mi][ni][e] = 0.0f;

    auto issue = [&](int chunk, int buf) {
        const unsigned st = sb + (unsigned)buf * STAGE_B;
        const long long ko = (long long)chunk * 32;
        cp16(st + adst,                       Ah + a_src + ko);
        cp16(st + 10240u + adst,              Al + a_src + ko);
        cp16(st + 20480u + adst,              Bh + b_src0 + ko);
        cp16(st + 20480u + 10240u + adst,     Bh + b_src1 + ko);
        cp16(st + 40960u + adst,              Bl + b_src0 + ko);
        cp16(st + 40960u + 10240u + adst,     Bl + b_src1 + ko);
        asm volatile("cp.async.commit_group;" ::: "memory");
    };

    issue(c0, 0);
    issue(c0 + 1, 1);

    int buf_t = 0;
    for (int t = 0; t < cn; t++) {
        // ensure group for tile t has landed
        if (t + 1 < cn) asm volatile("cp.async.wait_group 1;" ::: "memory");
        else            asm volatile("cp.async.wait_group 0;" ::: "memory");
        __syncthreads();   // also protects slot (t-1)%3 from the issue below
        if (t + 2 < cn) {
            int b2 = buf_t + 2; if (b2 >= 3) b2 -= 3;
            issue(c0 + t + 2, b2);
        }
        const unsigned st = sb + (unsigned)buf_t * STAGE_B;
#pragma unroll
        for (int ks = 0; ks < 2; ks++) {
            unsigned bh[2][4], bl[2][4];
#pragma unroll
            for (int p = 0; p < 2; p++) {
                ldsm4(bh[p], st + 20480u + b_lane + p * 1280u + ks * 32u);
                ldsm4(bl[p], st + 40960u + b_lane + p * 1280u + ks * 32u);
            }
#pragma unroll
            for (int mi = 0; mi < 4; mi++) {
                unsigned ah[4], al[4];
                ldsm4(ah, st + a_lane + mi * 1280u + ks * 32u);
                ldsm4(al, st + 10240u + a_lane + mi * 1280u + ks * 32u);
#pragma unroll
                for (int ni = 0; ni < 4; ni++) {
                    const int p = ni >> 1, h = (ni & 1) * 2;
                    mma16816(acc[mi][ni], ah, bh[p][h], bh[p][h + 1]);  // hi*hi
                    mma16816(acc[mi][ni], al, bh[p][h], bh[p][h + 1]);  // lo*hi
                    mma16816(acc[mi][ni], ah, bl[p][h], bl[p][h + 1]);  // hi*lo
                }
            }
        }
        if (++buf_t == 3) buf_t = 0;
    }

    // epilogue (registers -> gmem only; no smem dependence)
    float* Cz = C + z * zstride;
    const int er = bm + warp_m * 64 + (lane >> 2);
    const int ec = bn + warp_n * 32 + (lane & 3) * 2;
#pragma unroll
    for (int mi = 0; mi < 4; mi++)
#pragma unroll
        for (int ni = 0; ni < 4; ni++) {
            const int col = ec + ni * 8;
            if (col < Ncols) {
                float bv0 = BIAS ? bias[col] : 0.0f;
                float bv1 = BIAS ? bias[col + 1] : 0.0f;
                const int row = er + mi * 16;
                *(float2*)&Cz[(long long)row * ldc + col] =
                    make_float2(acc[mi][ni][0] + bv0, acc[mi][ni][1] + bv1);
                *(float2*)&Cz[(long long)(row + 8) * ldc + col] =
                    make_float2(acc[mi][ni][2] + bv0, acc[mi][ni][3] + bv1);
            }
        }
}

// ---------------- adjacency build ----------------
__global__ void k_zero(float* scratch) {
    int i = blockIdx.x * blockDim.x + threadIdx.x;
    if (i < NNODE * NNODE + NNODE) scratch[i] = 0.0f;
}
__global__ void k_count(float* scratch, const int* __restrict__ src,
                        const int* __restrict__ dst) {
    int e = blockIdx.x * blockDim.x + threadIdx.x;
    if (e < NE) {
        int d = dst[e], s = src[e];
        atomicAdd(&scratch[OFF_A + d * NNODE + s], 1.0f);
        atomicAdd(&scratch[OFF_DEG + d], 1.0f);
    }
}
__global__ void k_norm(float* scratch) {
    int i = blockIdx.x * blockDim.x + threadIdx.x;
    if (i < NNODE * NNODE) {
        float d = scratch[OFF_DEG + (i >> 9)];
        scratch[OFF_A + i] = scratch[OFF_A + i] / fmaxf(d, 1.0f);
    }
}

// ---------------- FFMA2 SIMT kernels (mid-size GEMMs; validated) ----------------
__device__ __forceinline__ unsigned long long pack2(float a, float b) {
    unsigned long long r;
    asm("mov.b64 %0, {%1, %2};" : "=l"(r) : "f"(a), "f"(b));
    return r;
}
__device__ __forceinline__ void unpack2(unsigned long long v, float& a, float& b) {
    asm("mov.b64 {%0, %1}, %2;" : "=f"(a), "=f"(b) : "l"(v));
}
__device__ __forceinline__ unsigned long long ffma2(unsigned long long a,
                                                    unsigned long long b,
                                                    unsigned long long c) {
    unsigned long long d;
    asm("fma.rn.f32x2 %0, %1, %2, %3;" : "=l"(d) : "l"(a), "l"(b), "l"(c));
    return d;
}

template <int BM, int BN, int TM, int TN>
__device__ __forceinline__ void compute_tile(const float (*As)[BM + 4],
                                             const float (*Bs)[BN + 4],
                                             int ty, int tx,
                                             unsigned long long acc[TM / 2][TN]) {
#pragma unroll
    for (int kk = 0; kk < 16; kk++) {
        unsigned long long aa[TM / 2];
#pragma unroll
        for (int i = 0; i < TM / 2; i += 2) {
            ulonglong2 av = *reinterpret_cast<const ulonglong2*>(&As[kk][ty * TM + 2 * i]);
            aa[i] = av.x;
            if (i + 1 < TM / 2) aa[i + 1] = av.y;
        }
        float4 bvv = *reinterpret_cast<const float4*>(&Bs[kk][tx * TN]);
        unsigned long long bb[4];
        bb[0] = pack2(bvv.x, bvv.x);
        bb[1] = pack2(bvv.y, bvv.y);
        bb[2] = pack2(bvv.z, bvv.z);
        bb[3] = pack2(bvv.w, bvv.w);
#pragma unroll
        for (int i = 0; i < TM / 2; i++)
#pragma unroll
            for (int j = 0; j < TN; j++)
                acc[i][j] = ffma2(aa[i], bb[j], acc[i][j]);
    }
}

template <int BM, int BN, int TM, int TN, bool ZC0, bool RELU, bool BIAS>
__global__ __launch_bounds__(256, 2)
void gemm_nt(const float* __restrict__ A, int lda,
             const float* __restrict__ B, int ldb,
             const float* __restrict__ bias,
             float* __restrict__ C, int ldc,
             int Ncols, int K) {
    constexpr int BK = 16;
    __shared__ float As[BK][BM + 4];
    __shared__ float Bs[BK][BN + 4];
    const int tid = threadIdx.x;
    const int tx = tid & 15, ty = tid >> 4;
    const int bm = blockIdx.y * BM, bn = blockIdx.x * BN;
    const int lm = tid >> 4, lk = tid & 15;
    constexpr int ASL = BM * BK / 256, BSL = BN * BK / 256;
    float ar[ASL], br[BSL];
    unsigned long long acc[TM / 2][TN];
#pragma unroll
    for (int i = 0; i < TM / 2; i++)
#pragma unroll
        for (int j = 0; j < TN; j++) acc[i][j] = 0ull;
    const int ktiles = (K + BK - 1) / BK;
    {
        const int k = lk;
#pragma unroll
        for (int s = 0; s < ASL; s++) {
            float v = 0.0f;
            if (k < K) { v = A[(bm + lm + s * 16) * lda + k]; if (ZC0 && k == 0) v = 0.0f; }
            ar[s] = v;
        }
#pragma unroll
        for (int s = 0; s < BSL; s++) {
            int n = bn + lm + s * 16;
            float v = 0.0f;
            if (k < K && n < Ncols) v = B[n * ldb + k];
            br[s] = v;
        }
    }
    for (int t = 0; t < ktiles; t++) {
        __syncthreads();
#pragma unroll
        for (int s = 0; s < ASL; s++) As[lk][lm + s * 16] = ar[s];
#pragma unroll
        for (int s = 0; s < BSL; s++) Bs[lk][lm + s * 16] = br[s];
        __syncthreads();
        if (t + 1 < ktiles) {
            const int k = (t + 1) * BK + lk;
#pragma unroll
            for (int s = 0; s < ASL; s++) {
                float v = 0.0f;
                if (k < K) { v = A[(bm + lm + s * 16) * lda + k]; if (ZC0 && k == 0) v = 0.0f; }
                ar[s] = v;
            }
#pragma unroll
            for (int s = 0; s < BSL; s++) {
                int n = bn + lm + s * 16;
                float v = 0.0f;
                if (k < K && n < Ncols) v = B[n * ldb + k];
                br[s] = v;
            }
        }
        compute_tile<BM, BN, TM, TN>(As, Bs, ty, tx, acc);
    }
#pragma unroll
    for (int j = 0; j < TN; j++) {
        const int n = bn + tx * TN + j;
        if (n >= Ncols) continue;
        float bv = BIAS ? bias[n] : 0.0f;
#pragma unroll
        for (int i = 0; i < TM / 2; i++) {
            float c0, c1;
            unpack2(acc[i][j], c0, c1);
            c0 += bv; c1 += bv;
            if (RELU) { c0 = fmaxf(c0, 0.0f); c1 = fmaxf(c1, 0.0f); }
            const int m0 = bm + ty * TM + 2 * i;
            C[m0 * ldc + n] = c0;
            C[(m0 + 1) * ldc + n] = c1;
        }
    }
}

template <int MODE>
__global__ __launch_bounds__(256, 2)
void gemm_nn64(const float* __restrict__ A, int lda,
               const float* __restrict__ B, int ldb, int jstr,
               const float* __restrict__ qeven, const float* __restrict__ bias,
               float* __restrict__ C, int ldc, int K) {
    constexpr int BM = 64, BN = 64, BK = 16, TM = 4, TN = 4;
    __shared__ float As[BK][BM + 4];
    __shared__ float Bs[BK][BN + 4];
    const int tid = threadIdx.x;
    const int tx = tid & 15, ty = tid >> 4;
    const int bm = blockIdx.y * BM, bn = blockIdx.x * BN;
    const int lm = tid >> 4, lk = tid & 15;
    const int bkk = tid >> 6, bnn = tid & 63;
    float ar[4], br[4];
    unsigned long long acc[2][4];
#pragma unroll
    for (int i = 0; i < 2; i++)
#pragma unroll
        for (int j = 0; j < 4; j++) acc[i][j] = 0ull;
    const int ktiles = K / BK;
    {
#pragma unroll
        for (int s = 0; s < 4; s++) ar[s] = A[(bm + lm + s * 16) * lda + lk];
#pragma unroll
        for (int s = 0; s < 4; s++) br[s] = B[(bkk + s * 4) * ldb + (bn + bnn) * jstr];
    }
    for (int t = 0; t < ktiles; t++) {
        __syncthreads();
#pragma unroll
        for (int s = 0; s < 4; s++) As[lk][lm + s * 16] = ar[s];
#pragma unroll
        for (int s = 0; s < 4; s++) Bs[bkk + s * 4][bnn] = br[s];
        __syncthreads();
        if (t + 1 < ktiles) {
            const int k0 = (t + 1) * BK;
#pragma unroll
            for (int s = 0; s < 4; s++) ar[s] = A[(bm + lm + s * 16) * lda + k0 + lk];
#pragma unroll
            for (int s = 0; s < 4; s++)
                br[s] = B[(k0 + bkk + s * 4) * ldb + (bn + bnn) * jstr];
        }
        compute_tile<BM, BN, TM, TN>(As, Bs, ty, tx, acc);
    }
#pragma unroll
    for (int j = 0; j < 4; j++) {
        const int n = bn + tx * TN + j;
#pragma unroll
        for (int i = 0; i < 2; i++) {
            float c0, c1;
            unpack2(acc[i][j], c0, c1);
            const int m0 = bm + ty * TM + 2 * i;
            if (MODE == 1) {
                float bv = bias[n];
                c0 = fmaxf(c0 + qeven[m0 * QN + 2 * n] + bv, 0.0f);
                c1 = fmaxf(c1 + qeven[(m0 + 1) * QN + 2 * n] + bv, 0.0f);
            }
            C[m0 * ldc + n] = c0;
            C[(m0 + 1) * ldc + n] = c1;
        }
    }
}

// ---------------- launcher ----------------
extern "C" void kernel_launch(void* const* d_in, const int* in_sizes, int n_in,
                              void* d_out, int out_size) {
    (void)in_sizes; (void)n_in; (void)out_size;
    const float* x    = (const float*)d_in[0];
    const int*   esrc = (const int*)d_in[1];
    const int*   edst = (const int*)d_in[2];
    const float* W_e2 = (const float*)d_in[3];
    const float* b_e2 = (const float*)d_in[4];
    const float* W_e3 = (const float*)d_in[5];
    const float* b_e3 = (const float*)d_in[6];
    const float* W_d1 = (const float*)d_in[7];
    const float* b_d1 = (const float*)d_in[8];
    const float* W_d3 = (const float*)d_in[9];
    const float* b_d3 = (const float*)d_in[10];

    float* out = (float*)d_out;
    float* enc = out;
    float* dec = out + NNODE * EMBD;

    float* scratch = nullptr;
    cudaGetSymbolAddress((void**)&scratch, g_scratch);
    float* A_  = scratch + OFF_A;
    float* Q_  = scratch + OFF_Q;
    float* T1_ = scratch + OFF_T1;
    float* H_  = scratch + OFF_H;
    float* HD_ = scratch + OFF_HD;
    float* P_  = scratch + OFF_P;

    unsigned short *xh, *xl, *vh, *vl, *wh, *wl, *hh, *hl;
    cudaGetSymbolAddress((void**)&xh, g_xh); cudaGetSymbolAddress((void**)&xl, g_xl);
    cudaGetSymbolAddress((void**)&vh, g_vh); cudaGetSymbolAddress((void**)&vl, g_vl);
    cudaGetSymbolAddress((void**)&wh, g_wh); cudaGetSymbolAddress((void**)&wl, g_wl);
    cudaGetSymbolAddress((void**)&hh, g_hh); cudaGetSymbolAddress((void**)&hl, g_hl);

    static int smem_set = 0;
    if (!smem_set) {
        cudaFuncSetAttribute(gemm_mma<false, false>,
                             cudaFuncAttributeMaxDynamicSharedMemorySize, 3 * STAGE_B);
        cudaFuncSetAttribute(gemm_mma<true, true>,
                             cudaFuncAttributeMaxDynamicSharedMemorySize, 3 * STAGE_B);
        smem_set = 1;
    }

    const int KQ8a = KPAD1 / 8;   // 2256
    const int KQ8b = KPAD2 / 8;   // 96

    // launches 1-3: bf16 hi/lo splits (x with col-0 zeroed)
    k_split_f<KPAD1 / 8><<<(NNODE * KQ8a + 255) / 256, 256>>>(x, xh, xl, NNODE, FD, 1);
    k_split_f<KPAD1 / 8><<<(QN * KQ8a + 255) / 256, 256>>>(W_e2, vh, vl, QN, FD, 0);
    k_split_f<KPAD2 / 8><<<(OUTD * KQ8b + 255) / 256, 256>>>(W_d3, wh, wl, OUTD, H2D, 0);

    // launch 4 (ncu captures launch #4): Q = x' @ V^T, HMMA split-K=6
    gemm_mma<false, false><<<dim3(QN / 256, NNODE / 128, NSPLIT), 512, 3 * STAGE_B>>>(
        xh, xl, KPAD1, vh, vl, KPAD1, nullptr, P_, QN, QN,
        (long long)NNODE * QN, CH1, NSPLIT);

    // adjacency (independent of GEMM1; launches 5-7)
    k_zero <<<(NNODE * NNODE + NNODE + 255) / 256, 256>>>(scratch);
    k_count<<<(NE + 255) / 256, 256>>>(scratch, esrc, edst);
    k_norm <<<(NNODE * NNODE + 255) / 256, 256>>>(scratch);

    k_combine<<<(NNODE * QN + 255) / 256, 256>>>(P_, Q_);

    // T1 = A @ Qodd
    gemm_nn64<0><<<dim3(H2D / 64, NNODE / 64), 256>>>(
        A_, NNODE, Q_ + 1, QN, 2, nullptr, nullptr, T1_, H2D, NNODE);

    // H = relu(Qeven + A @ T1 + b_e2)
    gemm_nn64<1><<<dim3(H2D / 64, NNODE / 64), 256>>>(
        A_, NNODE, T1_, H2D, 1, Q_, b_e2, H_, H2D, NNODE);

    // encoded = H @ W_e3^T + b_e3
    gemm_nt<64, 64, 4, 4, false, false, true>
        <<<dim3(EMBD / 64, NNODE / 64), 256>>>(H_, H2D, W_e3, H2D, b_e3, enc, EMBD, EMBD, H2D);

    // HD = relu(encoded @ W_d1^T + b_d1)
    gemm_nt<64, 64, 4, 4, false, true, true>
        <<<dim3(H2D / 64, NNODE / 64), 256>>>(enc, EMBD, W_d1, EMBD, b_d1, HD_, H2D, H2D, EMBD);

    // split HD, then decoded = HD @ W_d3^T + b_d3 (HMMA; grid swapped for wave locality)
    k_split_f<KPAD2 / 8><<<(NNODE * KQ8b + 255) / 256, 256>>>(HD_, hh, hl, NNODE, H2D, 0);
    gemm_mma<true, true><<<dim3(NNODE / 128, NDPAD / 256, 1), 512, 3 * STAGE_B>>>(
        hh, hl, KPAD2, wh, wl, KPAD2, b_d3, dec, OUTD, OUTD,
        0ll, CH2, 1);
}